// round 2
// baseline (speedup 1.0000x reference)
#include <cuda_runtime.h>

#define NE    100000
#define DIM   128
#define NB    4
#define NRL   8
#define NEDGE 200000

typedef unsigned long long ull;

// Scratch: Z[node][b][o] = sum_i H[node,i] * V[b,i,o]   (204.8 MB)
__device__ float g_Z[(size_t)NE * (NB * DIM)];

struct f32x2 { float lo, hi; };

#if defined(__CUDA_ARCH__) && (__CUDA_ARCH__ >= 1000)
#define USE_F32X2 1
#else
#define USE_F32X2 0
#endif

__device__ __forceinline__ ull pack2(float x) {
#if USE_F32X2
    unsigned int u = __float_as_uint(x);
    ull r;
    asm("mov.b64 %0, {%1, %1};" : "=l"(r) : "r"(u));
    return r;
#else
    f32x2 v; v.lo = x; v.hi = x;
    return *reinterpret_cast<ull*>(&v);
#endif
}
__device__ __forceinline__ void fma2(ull& d, ull a, ull b) {
#if USE_F32X2
    asm("fma.rn.f32x2 %0, %1, %2, %3;" : "=l"(d) : "l"(a), "l"(b), "l"(d));
#else
    f32x2 dv = *reinterpret_cast<f32x2*>(&d);
    f32x2 av = *reinterpret_cast<f32x2*>(&a);
    f32x2 bv = *reinterpret_cast<f32x2*>(&b);
    dv.lo = fmaf(av.lo, bv.lo, dv.lo);
    dv.hi = fmaf(av.hi, bv.hi, dv.hi);
    d = *reinterpret_cast<ull*>(&dv);
#endif
}
__device__ __forceinline__ void unpack2(ull v, float& lo, float& hi) {
    f32x2 x = *reinterpret_cast<f32x2*>(&v);
    lo = x.lo; hi = x.hi;
}

__global__ void zero_kernel(float4* __restrict__ out, int n4) {
    int stride = gridDim.x * blockDim.x;
    for (int i = blockIdx.x * blockDim.x + threadIdx.x; i < n4; i += stride)
        out[i] = make_float4(0.f, 0.f, 0.f, 0.f);
}

// Z[n, b*128 + o] = sum_i H[n,i] * V[b,i,o]
// Block: 128 nodes x 64 outputs of one basis. blockIdx.y = b*2 + (output half).
// Per thread: 8 nodes x 4 outputs (2 f32x2 pairs), packed FFMA2 inner loop.
__global__ __launch_bounds__(256) void zgemm_kernel(const float* __restrict__ H,
                                                    const float* __restrict__ V) {
    __shared__ float Hs[32][132];   // [i][n], padded to kill store bank conflicts
    __shared__ float Vs[32][64];    // [i][o]

    const int b     = blockIdx.y >> 1;
    const int oBase = (blockIdx.y & 1) * 64;
    const int n0    = blockIdx.x * 128;
    const int t     = threadIdx.x;
    const int tn    = t & 15;        // node group 0..15
    const int to    = t >> 4;        // output group 0..15
    const int myN   = tn * 8;        // 8 nodes
    const int myO   = to * 4;        // 4 outputs

    ull acc[8][2];
#pragma unroll
    for (int n = 0; n < 8; n++) { acc[n][0] = 0ull; acc[n][1] = 0ull; }

    for (int kk = 0; kk < 128; kk += 32) {
        __syncthreads();
        // Load H chunk, transposed into Hs[i][n]
#pragma unroll
        for (int q = 0; q < 4; q++) {
            int idx = t + 256 * q;          // 0..1023
            int nn  = idx >> 3;             // 0..127
            int ii  = (idx & 7) * 4;        // 0,4,...,28
            float4 hv = make_float4(0.f, 0.f, 0.f, 0.f);
            int gn = n0 + nn;
            if (gn < NE)
                hv = *reinterpret_cast<const float4*>(&H[(size_t)gn * DIM + kk + ii]);
            Hs[ii + 0][nn] = hv.x;
            Hs[ii + 1][nn] = hv.y;
            Hs[ii + 2][nn] = hv.z;
            Hs[ii + 3][nn] = hv.w;
        }
        // Load V chunk: Vs[i][o] = V[b][kk+i][oBase+o]
#pragma unroll
        for (int q = 0; q < 2; q++) {
            int idx = t + 256 * q;          // 0..511
            int i   = idx >> 4;             // 0..31
            int oo  = (idx & 15) * 4;       // 0..60
            *reinterpret_cast<float4*>(&Vs[i][oo]) =
                *reinterpret_cast<const float4*>(
                    &V[((size_t)b * DIM + kk + i) * DIM + oBase + oo]);
        }
        __syncthreads();

#pragma unroll 4
        for (int i = 0; i < 32; i++) {
            float4 hA = *reinterpret_cast<const float4*>(&Hs[i][myN]);
            float4 hB = *reinterpret_cast<const float4*>(&Hs[i][myN + 4]);
            ull v0 = *reinterpret_cast<const ull*>(&Vs[i][myO]);
            ull v1 = *reinterpret_cast<const ull*>(&Vs[i][myO + 2]);
            ull h;
            h = pack2(hA.x); fma2(acc[0][0], h, v0); fma2(acc[0][1], h, v1);
            h = pack2(hA.y); fma2(acc[1][0], h, v0); fma2(acc[1][1], h, v1);
            h = pack2(hA.z); fma2(acc[2][0], h, v0); fma2(acc[2][1], h, v1);
            h = pack2(hA.w); fma2(acc[3][0], h, v0); fma2(acc[3][1], h, v1);
            h = pack2(hB.x); fma2(acc[4][0], h, v0); fma2(acc[4][1], h, v1);
            h = pack2(hB.y); fma2(acc[5][0], h, v0); fma2(acc[5][1], h, v1);
            h = pack2(hB.z); fma2(acc[6][0], h, v0); fma2(acc[6][1], h, v1);
            h = pack2(hB.w); fma2(acc[7][0], h, v0); fma2(acc[7][1], h, v1);
        }
    }

    // Store to Z[node][b*128 + oBase + myO .. +3]
#pragma unroll
    for (int n = 0; n < 8; n++) {
        int gn = n0 + myN + n;
        if (gn < NE) {
            float4 r;
            unpack2(acc[n][0], r.x, r.y);
            unpack2(acc[n][1], r.z, r.w);
            *reinterpret_cast<float4*>(
                &g_Z[(size_t)gn * (NB * DIM) + b * DIM + oBase + myO]) = r;
        }
    }
}

// One warp per edge: out[row] += val * sum_b A[r,b] * Z[col][b][:]
__global__ __launch_bounds__(256) void scatter_kernel(const int* __restrict__ erow,
                                                      const int* __restrict__ ecol,
                                                      const float* __restrict__ eval,
                                                      const float* __restrict__ A,
                                                      float* __restrict__ out) {
    const int lane  = threadIdx.x & 31;
    int warp        = (blockIdx.x * blockDim.x + threadIdx.x) >> 5;
    const int nwarp = (gridDim.x * blockDim.x) >> 5;

    for (int e = warp; e < NRL * NEDGE; e += nwarp) {
        int r     = e / NEDGE;
        int col   = __ldg(&ecol[e]);
        int row   = __ldg(&erow[e]);
        float val = __ldg(&eval[e]);
        float c0 = val * __ldg(&A[r * NB + 0]);
        float c1 = val * __ldg(&A[r * NB + 1]);
        float c2 = val * __ldg(&A[r * NB + 2]);
        float c3 = val * __ldg(&A[r * NB + 3]);

        const float4* z = reinterpret_cast<const float4*>(&g_Z[(size_t)col * (NB * DIM)]);
        float4 z0 = __ldg(&z[lane]);
        float4 z1 = __ldg(&z[32 + lane]);
        float4 z2 = __ldg(&z[64 + lane]);
        float4 z3 = __ldg(&z[96 + lane]);

        float4 a;
        a.x = fmaf(c3, z3.x, fmaf(c2, z2.x, fmaf(c1, z1.x, c0 * z0.x)));
        a.y = fmaf(c3, z3.y, fmaf(c2, z2.y, fmaf(c1, z1.y, c0 * z0.y)));
        a.z = fmaf(c3, z3.z, fmaf(c2, z2.z, fmaf(c1, z1.z, c0 * z0.z)));
        a.w = fmaf(c3, z3.w, fmaf(c2, z2.w, fmaf(c1, z1.w, c0 * z0.w)));

        float* p = out + (size_t)row * DIM + lane * 4;
        asm volatile("red.global.add.v4.f32 [%0], {%1, %2, %3, %4};"
                     :: "l"(p), "f"(a.x), "f"(a.y), "f"(a.z), "f"(a.w)
                     : "memory");
    }
}

extern "C" void kernel_launch(void* const* d_in, const int* in_sizes, int n_in,
                              void* d_out, int out_size) {
    const float* H    = (const float*)d_in[0];
    const float* A    = (const float*)d_in[1];
    const float* V    = (const float*)d_in[2];
    const int*   erow = (const int*)d_in[3];
    const int*   ecol = (const int*)d_in[4];
    const float* eval = (const float*)d_in[5];
    float*       out  = (float*)d_out;

    int n4 = NE * DIM / 4;
    zero_kernel<<<(n4 + 255) / 256, 256>>>((float4*)out, n4);

    dim3 g((NE + 127) / 128, 8);   // y = basis*2 + output-half
    zgemm_kernel<<<g, 256>>>(H, V);

    scatter_kernel<<<1776, 256>>>(erow, ecol, eval, A, out);
}

// round 5
// speedup vs baseline: 1.6499x; 1.6499x over previous
#include <cuda_runtime.h>

#define NE    100000
#define DIM   128
#define NB    4
#define NRL   8
#define NEDGE 200000
#define NET   (NRL * NEDGE)   // 1,600,000 edges total
#define KTOT  (NB * DIM)      // 512

typedef unsigned long long ull;

// ---- device scratch (allocation-free rule: __device__ globals) ----
__device__ int   g_hist[NE];
__device__ int   g_off[NE];
__device__ int   g_cursor[NE];
__device__ ull   g_sorted[NET];                 // packed (col | r<<20, val)
__device__ float g_S[(size_t)NE * KTOT];        // S'[node][b*128+i]  (204.8 MB)

struct f32x2 { float lo, hi; };

#if defined(__CUDA_ARCH__) && (__CUDA_ARCH__ >= 1000)
#define USE_F32X2 1
#else
#define USE_F32X2 0
#endif

__device__ __forceinline__ void fma2(ull& d, ull a, ull b) {
#if USE_F32X2
    asm("fma.rn.f32x2 %0, %1, %2, %3;" : "=l"(d) : "l"(a), "l"(b), "l"(d));
#else
    f32x2 dv = *reinterpret_cast<f32x2*>(&d);
    f32x2 av = *reinterpret_cast<f32x2*>(&a);
    f32x2 bv = *reinterpret_cast<f32x2*>(&b);
    dv.lo = fmaf(av.lo, bv.lo, dv.lo);
    dv.hi = fmaf(av.hi, bv.hi, dv.hi);
    d = *reinterpret_cast<ull*>(&dv);
#endif
}
__device__ __forceinline__ ull pack2(float x) {
    unsigned int u = __float_as_uint(x);
    ull r;
    asm("mov.b64 %0, {%1, %1};" : "=l"(r) : "r"(u));
    return r;
}
__device__ __forceinline__ void unpack2(ull v, float& lo, float& hi) {
    f32x2 x = *reinterpret_cast<f32x2*>(&v);
    lo = x.lo; hi = x.hi;
}

// ---- launch 0: zero the row histogram ----
__global__ void zero_hist_kernel() {
    int stride = gridDim.x * blockDim.x;
    for (int i = blockIdx.x * blockDim.x + threadIdx.x; i < NE; i += stride)
        g_hist[i] = 0;
}

// ---- launch 1: row histogram ----
__global__ void hist_kernel(const int* __restrict__ erow) {
    int stride = gridDim.x * blockDim.x;
    for (int i = blockIdx.x * blockDim.x + threadIdx.x; i < NET; i += stride)
        atomicAdd(&g_hist[erow[i]], 1);
}

// ---- launch 2: single-block exclusive scan over g_hist -> g_off, g_cursor ----
__global__ void scan_kernel() {
    __shared__ int wsum[32];
    __shared__ int s_tot;
    __shared__ int s_carry;
    const int t = threadIdx.x, lane = t & 31, wid = t >> 5;
    if (t == 0) s_carry = 0;
    __syncthreads();

    for (int base = 0; base < NE; base += 1024) {
        int i = base + t;
        int v = (i < NE) ? g_hist[i] : 0;
        // inclusive warp scan
        int x = v;
#pragma unroll
        for (int d = 1; d < 32; d <<= 1) {
            int y = __shfl_up_sync(0xFFFFFFFFu, x, d);
            if (lane >= d) x += y;
        }
        if (lane == 31) wsum[wid] = x;
        __syncthreads();
        if (wid == 0) {
            int s = wsum[lane];
            int xs = s;
#pragma unroll
            for (int d = 1; d < 32; d <<= 1) {
                int y = __shfl_up_sync(0xFFFFFFFFu, xs, d);
                if (lane >= d) xs += y;
            }
            wsum[lane] = xs - s;            // exclusive warp prefix
            if (lane == 31) s_tot = xs;     // block total
        }
        __syncthreads();
        int excl = x - v + wsum[wid] + s_carry;
        if (i < NE) { g_off[i] = excl; g_cursor[i] = excl; }
        __syncthreads();
        if (t == 0) s_carry += s_tot;
        __syncthreads();
    }
}

// ---- launch 3: bucket-scatter edges into row-sorted order ----
__global__ void binsort_kernel(const int* __restrict__ erow,
                               const int* __restrict__ ecol,
                               const float* __restrict__ eval) {
    int stride = gridDim.x * blockDim.x;
    for (int i = blockIdx.x * blockDim.x + threadIdx.x; i < NET; i += stride) {
        int row = erow[i];
        int col = ecol[i];
        float v = eval[i];
        int r = i / NEDGE;                         // relation id 0..7
        int pos = atomicAdd(&g_cursor[row], 1);
        ull rec = (ull)(unsigned)(col | (r << 20)) |
                  ((ull)__float_as_uint(v) << 32);
        g_sorted[pos] = rec;
    }
}

// ---- launch 4: warp per row, accumulate basis-weighted H gathers ----
__global__ __launch_bounds__(256) void gather_kernel(const float* __restrict__ H,
                                                     const float* __restrict__ A) {
    const int lane = threadIdx.x & 31;
    const int w = (blockIdx.x * blockDim.x + threadIdx.x) >> 5;
    float a_reg = __ldg(&A[lane]);   // A is exactly 32 floats [8][4]
    if (w >= NE) return;

    const int off = g_off[w];
    const int cnt = g_hist[w];

    float4 a0 = make_float4(0.f, 0.f, 0.f, 0.f);
    float4 a1 = a0, a2 = a0, a3 = a0;

    for (int j = 0; j < cnt; j++) {
        ull rec = __ldg(&g_sorted[off + j]);           // broadcast load
        int col = (int)(rec & 0xFFFFFu);
        int rb  = ((int)(rec >> 20) & 7) * 4;
        float v = __uint_as_float((unsigned)(rec >> 32));
        float c0 = v * __shfl_sync(0xFFFFFFFFu, a_reg, rb + 0);
        float c1 = v * __shfl_sync(0xFFFFFFFFu, a_reg, rb + 1);
        float c2 = v * __shfl_sync(0xFFFFFFFFu, a_reg, rb + 2);
        float c3 = v * __shfl_sync(0xFFFFFFFFu, a_reg, rb + 3);

        float4 h = __ldg(reinterpret_cast<const float4*>(
                             &H[(size_t)col * DIM]) + lane);
        a0.x = fmaf(c0, h.x, a0.x); a0.y = fmaf(c0, h.y, a0.y);
        a0.z = fmaf(c0, h.z, a0.z); a0.w = fmaf(c0, h.w, a0.w);
        a1.x = fmaf(c1, h.x, a1.x); a1.y = fmaf(c1, h.y, a1.y);
        a1.z = fmaf(c1, h.z, a1.z); a1.w = fmaf(c1, h.w, a1.w);
        a2.x = fmaf(c2, h.x, a2.x); a2.y = fmaf(c2, h.y, a2.y);
        a2.z = fmaf(c2, h.z, a2.z); a2.w = fmaf(c2, h.w, a2.w);
        a3.x = fmaf(c3, h.x, a3.x); a3.y = fmaf(c3, h.y, a3.y);
        a3.z = fmaf(c3, h.z, a3.z); a3.w = fmaf(c3, h.w, a3.w);
    }

    float4* s = reinterpret_cast<float4*>(&g_S[(size_t)w * KTOT]);
    s[lane]      = a0;   // basis 0, i = lane*4..lane*4+3
    s[32 + lane] = a1;
    s[64 + lane] = a2;
    s[96 + lane] = a3;
}

// ---- launch 5: out = S'' @ Vcat   (M=100000, K=512, N=128), FFMA2 ----
__global__ __launch_bounds__(256) void gemm_kernel(const float* __restrict__ V,
                                                   float* __restrict__ out) {
    __shared__ float Hs[32][132];   // [k][node], padded
    __shared__ float Vs[32][128];   // [k][o]

    const int n0  = blockIdx.x * 128;
    const int t   = threadIdx.x;
    const int tn  = t & 15;
    const int to  = t >> 4;
    const int myN = tn * 8;
    const int myO = to * 8;

    ull acc[8][4];
#pragma unroll
    for (int n = 0; n < 8; n++)
#pragma unroll
        for (int p = 0; p < 4; p++) acc[n][p] = 0ull;

    for (int kk = 0; kk < KTOT; kk += 32) {
        __syncthreads();
        // stage S chunk transposed: Hs[k][node]
#pragma unroll
        for (int q = 0; q < 4; q++) {
            int idx = t + 256 * q;       // 0..1023
            int nn  = idx >> 3;          // 0..127
            int ii  = (idx & 7) * 4;     // 0..28
            float4 sv = make_float4(0.f, 0.f, 0.f, 0.f);
            int gn = n0 + nn;
            if (gn < NE)
                sv = *reinterpret_cast<const float4*>(
                    &g_S[(size_t)gn * KTOT + kk + ii]);
            Hs[ii + 0][nn] = sv.x;
            Hs[ii + 1][nn] = sv.y;
            Hs[ii + 2][nn] = sv.z;
            Hs[ii + 3][nn] = sv.w;
        }
        // stage V chunk: Vs[k][o] = Vcat[kk+k][o]
#pragma unroll
        for (int q = 0; q < 4; q++) {
            int idx = t + 256 * q;       // 0..1023
            int i   = idx >> 5;          // 0..31
            int oo  = (idx & 31) * 4;    // 0..124
            *reinterpret_cast<float4*>(&Vs[i][oo]) =
                *reinterpret_cast<const float4*>(&V[(size_t)(kk + i) * DIM + oo]);
        }
        __syncthreads();

#pragma unroll 2
        for (int i = 0; i < 32; i++) {
            float4 hA = *reinterpret_cast<const float4*>(&Hs[i][myN]);
            float4 hB = *reinterpret_cast<const float4*>(&Hs[i][myN + 4]);
            ulonglong2 va = *reinterpret_cast<const ulonglong2*>(&Vs[i][myO]);
            ulonglong2 vb = *reinterpret_cast<const ulonglong2*>(&Vs[i][myO + 4]);
            ull h;
            h = pack2(hA.x); fma2(acc[0][0], h, va.x); fma2(acc[0][1], h, va.y);
                             fma2(acc[0][2], h, vb.x); fma2(acc[0][3], h, vb.y);
            h = pack2(hA.y); fma2(acc[1][0], h, va.x); fma2(acc[1][1], h, va.y);
                             fma2(acc[1][2], h, vb.x); fma2(acc[1][3], h, vb.y);
            h = pack2(hA.z); fma2(acc[2][0], h, va.x); fma2(acc[2][1], h, va.y);
                             fma2(acc[2][2], h, vb.x); fma2(acc[2][3], h, vb.y);
            h = pack2(hA.w); fma2(acc[3][0], h, va.x); fma2(acc[3][1], h, va.y);
                             fma2(acc[3][2], h, vb.x); fma2(acc[3][3], h, vb.y);
            h = pack2(hB.x); fma2(acc[4][0], h, va.x); fma2(acc[4][1], h, va.y);
                             fma2(acc[4][2], h, vb.x); fma2(acc[4][3], h, vb.y);
            h = pack2(hB.y); fma2(acc[5][0], h, va.x); fma2(acc[5][1], h, va.y);
                             fma2(acc[5][2], h, vb.x); fma2(acc[5][3], h, vb.y);
            h = pack2(hB.z); fma2(acc[6][0], h, va.x); fma2(acc[6][1], h, va.y);
                             fma2(acc[6][2], h, vb.x); fma2(acc[6][3], h, vb.y);
            h = pack2(hB.w); fma2(acc[7][0], h, va.x); fma2(acc[7][1], h, va.y);
                             fma2(acc[7][2], h, vb.x); fma2(acc[7][3], h, vb.y);
        }
    }

#pragma unroll
    for (int n = 0; n < 8; n++) {
        int gn = n0 + myN + n;
        if (gn < NE) {
            float4 r0, r1;
            unpack2(acc[n][0], r0.x, r0.y);
            unpack2(acc[n][1], r0.z, r0.w);
            unpack2(acc[n][2], r1.x, r1.y);
            unpack2(acc[n][3], r1.z, r1.w);
            float4* po = reinterpret_cast<float4*>(&out[(size_t)gn * DIM + myO]);
            po[0] = r0;
            po[1] = r1;
        }
    }
}

extern "C" void kernel_launch(void* const* d_in, const int* in_sizes, int n_in,
                              void* d_out, int out_size) {
    const float* H    = (const float*)d_in[0];
    const float* A    = (const float*)d_in[1];
    const float* V    = (const float*)d_in[2];
    const int*   erow = (const int*)d_in[3];
    const int*   ecol = (const int*)d_in[4];
    const float* eval = (const float*)d_in[5];
    float*       out  = (float*)d_out;

    zero_hist_kernel<<<196, 512>>>();                       // launch 0
    hist_kernel<<<3125, 512>>>(erow);                       // launch 1
    scan_kernel<<<1, 1024>>>();                             // launch 2
    binsort_kernel<<<3125, 512>>>(erow, ecol, eval);        // launch 3
    gather_kernel<<<(NE * 32 + 255) / 256, 256>>>(H, A);    // launch 4
    gemm_kernel<<<(NE + 127) / 128, 256>>>(V, out);         // launch 5 (ncu target)
}

// round 13
// speedup vs baseline: 2.3703x; 1.4367x over previous
#include <cuda_runtime.h>
#include <cstdint>

#define NE    100000
#define DIM   128
#define NB    4
#define NRL   8
#define NEDGE 200000
#define NET   (NRL * NEDGE)   // 1,600,000 edges total
#define KTOT  (NB * DIM)      // 512
#define KT2   (KTOT / 2)      // 256 uints per row (bf16 pairs)
#define KT4   (KTOT / 8)      // 64 uint4 per row

typedef unsigned long long ull;

// ---- device scratch (allocation-free rule: __device__ globals) ----
__device__ int      g_hist[NE];
__device__ int      g_off[NE];
__device__ int      g_cursor[NE];
__device__ ull      g_sorted[NET];                    // packed (col | r<<20, val)
__device__ unsigned g_Shi[(size_t)NE * KT2];          // 102.4 MB (bf16 hi pairs)
__device__ unsigned g_Slo[(size_t)NE * KT2];          // 102.4 MB (bf16 lo pairs)
__device__ unsigned g_Vthi[DIM * KT2];                // V^T hi  [o][k-pair]
__device__ unsigned g_Vtlo[DIM * KT2];                // V^T lo  [o][k-pair]

// ============================ helpers ============================

__device__ __forceinline__ uint32_t smem_u32(const void* p) {
    uint32_t a;
    asm("{ .reg .u64 t; cvta.to.shared.u64 t, %1; cvt.u32.u64 %0, t; }"
        : "=r"(a) : "l"(p));
    return a;
}

// bf2(x, y): packed bf16x2 with x in LOW half, y in HIGH half.
__device__ __forceinline__ unsigned bf2(float x, float y) {
    unsigned r;
    asm("cvt.rn.bf16x2.f32 %0, %1, %2;" : "=r"(r) : "f"(y), "f"(x));
    return r;
}
// split_pair: (hi_pair, lo_pair), value = hi + lo (to bf16 rounding of residual)
__device__ __forceinline__ uint2 split_pair(float x, float y) {
    unsigned h = bf2(x, y);
    float rx = x - __uint_as_float(h << 16);           // low bf16 -> f32 (exact)
    float ry = y - __uint_as_float(h & 0xFFFF0000u);   // high bf16 -> f32 (exact)
    unsigned l = bf2(rx, ry);
    return make_uint2(h, l);
}

__device__ __forceinline__ void ldm_x4(uint32_t* r, uint32_t addr) {
    asm volatile("ldmatrix.sync.aligned.m8n8.x4.shared.b16 {%0,%1,%2,%3}, [%4];"
                 : "=r"(r[0]), "=r"(r[1]), "=r"(r[2]), "=r"(r[3]) : "r"(addr));
}
__device__ __forceinline__ void mma_bf16(float* d, const uint32_t* a, const uint32_t* b) {
    asm volatile(
        "mma.sync.aligned.m16n8k16.row.col.f32.bf16.bf16.f32 "
        "{%0,%1,%2,%3}, {%4,%5,%6,%7}, {%8,%9}, {%0,%1,%2,%3};"
        : "+f"(d[0]), "+f"(d[1]), "+f"(d[2]), "+f"(d[3])
        : "r"(a[0]), "r"(a[1]), "r"(a[2]), "r"(a[3]), "r"(b[0]), "r"(b[1]));
}

// ============================ prep kernels ============================

// Vt[o][k] = V[k*128 + o], split into bf16 hi/lo pairs (2 k per thread)
__global__ void vprep_kernel(const float* __restrict__ V) {
    int idx = blockIdx.x * blockDim.x + threadIdx.x;
    if (idx >= DIM * KT2) return;
    int o  = idx >> 8;          // 0..127
    int kp = idx & 255;         // k-pair 0..255
    int k  = kp * 2;
    float v0 = V[(size_t)k * DIM + o];
    float v1 = V[(size_t)(k + 1) * DIM + o];
    uint2 s = split_pair(v0, v1);
    g_Vthi[o * KT2 + kp] = s.x;
    g_Vtlo[o * KT2 + kp] = s.y;
}

__global__ void zero_hist_kernel() {
    int stride = gridDim.x * blockDim.x;
    for (int i = blockIdx.x * blockDim.x + threadIdx.x; i < NE; i += stride)
        g_hist[i] = 0;
}

__global__ void hist_kernel(const int* __restrict__ erow) {
    int stride = gridDim.x * blockDim.x;
    for (int i = blockIdx.x * blockDim.x + threadIdx.x; i < NET; i += stride)
        atomicAdd(&g_hist[erow[i]], 1);
}

// single-block exclusive scan over g_hist -> g_off, g_cursor
__global__ void scan_kernel() {
    __shared__ int wsum[32];
    __shared__ int s_tot;
    __shared__ int s_carry;
    const int t = threadIdx.x, lane = t & 31, wid = t >> 5;
    if (t == 0) s_carry = 0;
    __syncthreads();

    for (int base = 0; base < NE; base += 1024) {
        int i = base + t;
        int v = (i < NE) ? g_hist[i] : 0;
        int x = v;
#pragma unroll
        for (int d = 1; d < 32; d <<= 1) {
            int y = __shfl_up_sync(0xFFFFFFFFu, x, d);
            if (lane >= d) x += y;
        }
        if (lane == 31) wsum[wid] = x;
        __syncthreads();
        if (wid == 0) {
            int s = wsum[lane];
            int xs = s;
#pragma unroll
            for (int d = 1; d < 32; d <<= 1) {
                int y = __shfl_up_sync(0xFFFFFFFFu, xs, d);
                if (lane >= d) xs += y;
            }
            wsum[lane] = xs - s;
            if (lane == 31) s_tot = xs;
        }
        __syncthreads();
        int excl = x - v + wsum[wid] + s_carry;
        if (i < NE) { g_off[i] = excl; g_cursor[i] = excl; }
        __syncthreads();
        if (t == 0) s_carry += s_tot;
        __syncthreads();
    }
}

__global__ void binsort_kernel(const int* __restrict__ erow,
                               const int* __restrict__ ecol,
                               const float* __restrict__ eval) {
    int stride = gridDim.x * blockDim.x;
    for (int i = blockIdx.x * blockDim.x + threadIdx.x; i < NET; i += stride) {
        int row = erow[i];
        int col = ecol[i];
        float v = eval[i];
        int r = i / NEDGE;
        int pos = atomicAdd(&g_cursor[row], 1);
        ull rec = (ull)(unsigned)(col | (r << 20)) |
                  ((ull)__float_as_uint(v) << 32);
        g_sorted[pos] = rec;
    }
}

// ---- warp per row: accumulate basis-weighted H gathers; write bf16 hi/lo S ----
__global__ __launch_bounds__(256) void gather_kernel(const float* __restrict__ H,
                                                     const float* __restrict__ A) {
    const int lane = threadIdx.x & 31;
    const int w = (blockIdx.x * blockDim.x + threadIdx.x) >> 5;
    float a_reg = __ldg(&A[lane]);   // A is exactly 32 floats [8][4]
    if (w >= NE) return;

    const int off = g_off[w];
    const int cnt = g_hist[w];

    float4 a0 = make_float4(0.f, 0.f, 0.f, 0.f);
    float4 a1 = a0, a2 = a0, a3 = a0;

    int j = 0;
    for (; j + 2 <= cnt; j += 2) {
        ull rec0 = __ldg(&g_sorted[off + j]);
        ull rec1 = __ldg(&g_sorted[off + j + 1]);
        int col0 = (int)(rec0 & 0xFFFFFu);
        int col1 = (int)(rec1 & 0xFFFFFu);
        float4 h0 = __ldg(reinterpret_cast<const float4*>(&H[(size_t)col0 * DIM]) + lane);
        float4 h1 = __ldg(reinterpret_cast<const float4*>(&H[(size_t)col1 * DIM]) + lane);

        {
            int rb = ((int)(rec0 >> 20) & 7) * 4;
            float v = __uint_as_float((unsigned)(rec0 >> 32));
            float c0 = v * __shfl_sync(0xFFFFFFFFu, a_reg, rb + 0);
            float c1 = v * __shfl_sync(0xFFFFFFFFu, a_reg, rb + 1);
            float c2 = v * __shfl_sync(0xFFFFFFFFu, a_reg, rb + 2);
            float c3 = v * __shfl_sync(0xFFFFFFFFu, a_reg, rb + 3);
            a0.x = fmaf(c0, h0.x, a0.x); a0.y = fmaf(c0, h0.y, a0.y);
            a0.z = fmaf(c0, h0.z, a0.z); a0.w = fmaf(c0, h0.w, a0.w);
            a1.x = fmaf(c1, h0.x, a1.x); a1.y = fmaf(c1, h0.y, a1.y);
            a1.z = fmaf(c1, h0.z, a1.z); a1.w = fmaf(c1, h0.w, a1.w);
            a2.x = fmaf(c2, h0.x, a2.x); a2.y = fmaf(c2, h0.y, a2.y);
            a2.z = fmaf(c2, h0.z, a2.z); a2.w = fmaf(c2, h0.w, a2.w);
            a3.x = fmaf(c3, h0.x, a3.x); a3.y = fmaf(c3, h0.y, a3.y);
            a3.z = fmaf(c3, h0.z, a3.z); a3.w = fmaf(c3, h0.w, a3.w);
        }
        {
            int rb = ((int)(rec1 >> 20) & 7) * 4;
            float v = __uint_as_float((unsigned)(rec1 >> 32));
            float c0 = v * __shfl_sync(0xFFFFFFFFu, a_reg, rb + 0);
            float c1 = v * __shfl_sync(0xFFFFFFFFu, a_reg, rb + 1);
            float c2 = v * __shfl_sync(0xFFFFFFFFu, a_reg, rb + 2);
            float c3 = v * __shfl_sync(0xFFFFFFFFu, a_reg, rb + 3);
            a0.x = fmaf(c0, h1.x, a0.x); a0.y = fmaf(c0, h1.y, a0.y);
            a0.z = fmaf(c0, h1.z, a0.z); a0.w = fmaf(c0, h1.w, a0.w);
            a1.x = fmaf(c1, h1.x, a1.x); a1.y = fmaf(c1, h1.y, a1.y);
            a1.z = fmaf(c1, h1.z, a1.z); a1.w = fmaf(c1, h1.w, a1.w);
            a2.x = fmaf(c2, h1.x, a2.x); a2.y = fmaf(c2, h1.y, a2.y);
            a2.z = fmaf(c2, h1.z, a2.z); a2.w = fmaf(c2, h1.w, a2.w);
            a3.x = fmaf(c3, h1.x, a3.x); a3.y = fmaf(c3, h1.y, a3.y);
            a3.z = fmaf(c3, h1.z, a3.z); a3.w = fmaf(c3, h1.w, a3.w);
        }
    }
    if (j < cnt) {
        ull rec = __ldg(&g_sorted[off + j]);
        int col = (int)(rec & 0xFFFFFu);
        int rb  = ((int)(rec >> 20) & 7) * 4;
        float v = __uint_as_float((unsigned)(rec >> 32));
        float c0 = v * __shfl_sync(0xFFFFFFFFu, a_reg, rb + 0);
        float c1 = v * __shfl_sync(0xFFFFFFFFu, a_reg, rb + 1);
        float c2 = v * __shfl_sync(0xFFFFFFFFu, a_reg, rb + 2);
        float c3 = v * __shfl_sync(0xFFFFFFFFu, a_reg, rb + 3);
        float4 h = __ldg(reinterpret_cast<const float4*>(&H[(size_t)col * DIM]) + lane);
        a0.x = fmaf(c0, h.x, a0.x); a0.y = fmaf(c0, h.y, a0.y);
        a0.z = fmaf(c0, h.z, a0.z); a0.w = fmaf(c0, h.w, a0.w);
        a1.x = fmaf(c1, h.x, a1.x); a1.y = fmaf(c1, h.y, a1.y);
        a1.z = fmaf(c1, h.z, a1.z); a1.w = fmaf(c1, h.w, a1.w);
        a2.x = fmaf(c2, h.x, a2.x); a2.y = fmaf(c2, h.y, a2.y);
        a2.z = fmaf(c2, h.z, a2.z); a2.w = fmaf(c2, h.w, a2.w);
        a3.x = fmaf(c3, h.x, a3.x); a3.y = fmaf(c3, h.y, a3.y);
        a3.z = fmaf(c3, h.z, a3.z); a3.w = fmaf(c3, h.w, a3.w);
    }

    // pack to bf16 hi/lo pairs and store (uint2 = 4 bf16)
    uint2* shi = reinterpret_cast<uint2*>(&g_Shi[(size_t)w * KT2]);
    uint2* slo = reinterpret_cast<uint2*>(&g_Slo[(size_t)w * KT2]);
    {
        uint2 p0 = split_pair(a0.x, a0.y);
        uint2 p1 = split_pair(a0.z, a0.w);
        shi[lane] = make_uint2(p0.x, p1.x);
        slo[lane] = make_uint2(p0.y, p1.y);
    }
    {
        uint2 p0 = split_pair(a1.x, a1.y);
        uint2 p1 = split_pair(a1.z, a1.w);
        shi[32 + lane] = make_uint2(p0.x, p1.x);
        slo[32 + lane] = make_uint2(p0.y, p1.y);
    }
    {
        uint2 p0 = split_pair(a2.x, a2.y);
        uint2 p1 = split_pair(a2.z, a2.w);
        shi[64 + lane] = make_uint2(p0.x, p1.x);
        slo[64 + lane] = make_uint2(p0.y, p1.y);
    }
    {
        uint2 p0 = split_pair(a3.x, a3.y);
        uint2 p1 = split_pair(a3.z, a3.w);
        shi[96 + lane] = make_uint2(p0.x, p1.x);
        slo[96 + lane] = make_uint2(p0.y, p1.y);
    }
}

// ============================ mma.sync GEMM ============================
// out[M=100000, N=128] = S[M, K=512] @ Vt^T, split bf16 (3 products),
// fp32 accumulate in registers. m16n8k16 HMMA, CTA tile 128x128, BK=32.
// B is stored [n][k] (k contiguous) == col-major KxN, so B fragments load
// with NON-transposed ldmatrix (each register = 2 consecutive k, fixed n).

#define BK       32
#define NCHUNK   (KTOT / BK)    // 16
#define SROW     80             // smem row stride bytes (32 bf16 + 8 pad)

__global__ __launch_bounds__(512, 1) void gemm_mma_kernel(float* __restrict__ out) {
    __shared__ __align__(16) unsigned char smAh[128 * SROW];
    __shared__ __align__(16) unsigned char smAl[128 * SROW];
    __shared__ __align__(16) unsigned char smBh[128 * SROW];
    __shared__ __align__(16) unsigned char smBl[128 * SROW];

    const int t    = threadIdx.x;
    const int lane = t & 31;
    const int wid  = t >> 5;          // 0..15
    const int wm   = wid >> 2;        // 0..3  (M group of 32 rows)
    const int wn   = wid & 3;         // 0..3  (N group of 32 cols)
    const int n0   = blockIdx.x * 128;

    // load mapping: 512 threads, one uint4 per array per thread per chunk
    const int lr = t >> 2;            // row 0..127
    const int lj = t & 3;             // uint4 0..3 within 32-bf16 row chunk
    const int gn = n0 + lr;
    const bool valid = gn < NE;
    const uint4* gAh = reinterpret_cast<const uint4*>(g_Shi) + (size_t)(valid ? gn : 0) * KT4;
    const uint4* gAl = reinterpret_cast<const uint4*>(g_Slo) + (size_t)(valid ? gn : 0) * KT4;
    const uint4* gBh = reinterpret_cast<const uint4*>(g_Vthi) + lr * KT4;
    const uint4* gBl = reinterpret_cast<const uint4*>(g_Vtlo) + lr * KT4;
    unsigned char* stAh = smAh + lr * SROW + lj * 16;
    unsigned char* stAl = smAl + lr * SROW + lj * 16;
    unsigned char* stBh = smBh + lr * SROW + lj * 16;
    unsigned char* stBl = smBl + lr * SROW + lj * 16;
    const uint4 z4 = make_uint4(0u, 0u, 0u, 0u);

    // ldmatrix lane addressing (constant across chunks)
    const uint32_t bAh = smem_u32(smAh), bAl = smem_u32(smAl);
    const uint32_t bBh = smem_u32(smBh), bBl = smem_u32(smBl);
    const int arow = lane & 15, acol = lane >> 4;            // A x4
    const int bgrp = lane >> 3, brow = lane & 7;             // B x4 (non-trans)
    // A tile mt (0..1), k-step ks2 (0..1): row = wm*32 + mt*16 + arow, kbyte = ks2*32 + acol*16
    // B pair ntp (0..1): row(n) = wn*32 + ntp*16 + (bgrp>>1)*8 + brow, kbyte = ks2*32 + (bgrp&1)*16
    //   tiles: lanes0-7 -> (n group 0, k0-7) = b0; 8-15 -> (n group 0, k8-15) = b1;
    //          16-23 -> (n group 1, k0-7);  24-31 -> (n group 1, k8-15)
    uint32_t aoff[2][2], boff[2][2];
#pragma unroll
    for (int ks2 = 0; ks2 < 2; ks2++) {
#pragma unroll
        for (int mt = 0; mt < 2; mt++)
            aoff[ks2][mt] = (uint32_t)((wm * 32 + mt * 16 + arow) * SROW + ks2 * 32 + acol * 16);
#pragma unroll
        for (int ntp = 0; ntp < 2; ntp++)
            boff[ks2][ntp] = (uint32_t)((wn * 32 + ntp * 16 + (bgrp >> 1) * 8 + brow) * SROW
                                        + ks2 * 32 + (bgrp & 1) * 16);
    }

    float d[2][4][4];
#pragma unroll
    for (int mt = 0; mt < 2; mt++)
#pragma unroll
        for (int nt = 0; nt < 4; nt++)
#pragma unroll
            for (int q = 0; q < 4; q++) d[mt][nt][q] = 0.f;

    for (int c = 0; c < NCHUNK; c++) {
        __syncthreads();
        *reinterpret_cast<uint4*>(stAh) = valid ? __ldg(&gAh[c * 4 + lj]) : z4;
        *reinterpret_cast<uint4*>(stAl) = valid ? __ldg(&gAl[c * 4 + lj]) : z4;
        *reinterpret_cast<uint4*>(stBh) = __ldg(&gBh[c * 4 + lj]);
        *reinterpret_cast<uint4*>(stBl) = __ldg(&gBl[c * 4 + lj]);
        __syncthreads();

#pragma unroll
        for (int ks2 = 0; ks2 < 2; ks2++) {
            uint32_t a_hi[2][4], a_lo[2][4], b_hi[4][2], b_lo[4][2];
#pragma unroll
            for (int mt = 0; mt < 2; mt++) {
                ldm_x4(a_hi[mt], bAh + aoff[ks2][mt]);
                ldm_x4(a_lo[mt], bAl + aoff[ks2][mt]);
            }
#pragma unroll
            for (int ntp = 0; ntp < 2; ntp++) {
                uint32_t r[4];
                ldm_x4(r, bBh + boff[ks2][ntp]);
                b_hi[ntp * 2][0] = r[0]; b_hi[ntp * 2][1] = r[1];
                b_hi[ntp * 2 + 1][0] = r[2]; b_hi[ntp * 2 + 1][1] = r[3];
                ldm_x4(r, bBl + boff[ks2][ntp]);
                b_lo[ntp * 2][0] = r[0]; b_lo[ntp * 2][1] = r[1];
                b_lo[ntp * 2 + 1][0] = r[2]; b_lo[ntp * 2 + 1][1] = r[3];
            }
#pragma unroll
            for (int mt = 0; mt < 2; mt++)
#pragma unroll
                for (int nt = 0; nt < 4; nt++) {
                    mma_bf16(d[mt][nt], a_hi[mt], b_hi[nt]);
                    mma_bf16(d[mt][nt], a_lo[mt], b_hi[nt]);
                    mma_bf16(d[mt][nt], a_hi[mt], b_lo[nt]);
                }
        }
    }

    // epilogue: fragment (lane) -> rows wm*32+mt*16+{l>>2, l>>2+8}, cols wn*32+nt*8+2*(l&3)
    const int erow = lane >> 2;
    const int ecol = (lane & 3) * 2;
#pragma unroll
    for (int mt = 0; mt < 2; mt++) {
#pragma unroll
        for (int nt = 0; nt < 4; nt++) {
            int r0 = n0 + wm * 32 + mt * 16 + erow;
            int cc = wn * 32 + nt * 8 + ecol;
            if (r0 < NE)
                *reinterpret_cast<float2*>(&out[(size_t)r0 * DIM + cc]) =
                    make_float2(d[mt][nt][0], d[mt][nt][1]);
            if (r0 + 8 < NE)
                *reinterpret_cast<float2*>(&out[(size_t)(r0 + 8) * DIM + cc]) =
                    make_float2(d[mt][nt][2], d[mt][nt][3]);
        }
    }
}

// ============================ launch ============================

extern "C" void kernel_launch(void* const* d_in, const int* in_sizes, int n_in,
                              void* d_out, int out_size) {
    const float* H    = (const float*)d_in[0];
    const float* A    = (const float*)d_in[1];
    const float* V    = (const float*)d_in[2];
    const int*   erow = (const int*)d_in[3];
    const int*   ecol = (const int*)d_in[4];
    const float* eval = (const float*)d_in[5];
    float*       out  = (float*)d_out;

    vprep_kernel<<<(DIM * KT2 + 255) / 256, 256>>>(V);
    zero_hist_kernel<<<196, 512>>>();
    hist_kernel<<<3125, 512>>>(erow);
    scan_kernel<<<1, 1024>>>();
    binsort_kernel<<<3125, 512>>>(erow, ecol, eval);
    gather_kernel<<<(NE * 32 + 255) / 256, 256>>>(H, A);        // launch 5 (ncu)
    gemm_mma_kernel<<<(NE + 127) / 128, 512>>>(out);
}

// round 14
// speedup vs baseline: 3.1228x; 1.3174x over previous
#include <cuda_runtime.h>
#include <cstdint>

#define NE    100000
#define DIM   128
#define NB    4
#define NRL   8
#define NEDGE 200000
#define NET   (NRL * NEDGE)   // 1,600,000 edges total
#define KTOT  (NB * DIM)      // 512
#define KT2   (KTOT / 2)      // 256 uints per row (bf16 pairs)
#define KT4   (KTOT / 8)      // 64 uint4 per row

typedef unsigned long long ull;

// ---- device scratch (allocation-free rule: __device__ globals) ----
__device__ int      g_hist[NE];
__device__ int      g_off[NE];
__device__ int      g_cursor[NE];
__device__ int      g_total;
__device__ ull      g_sorted[NET];                    // packed (col | r<<20, val)
__device__ unsigned g_Shi[(size_t)NE * KT2];          // 102.4 MB (bf16 hi pairs)
__device__ unsigned g_Slo[(size_t)NE * KT2];          // 102.4 MB (bf16 lo pairs)
__device__ unsigned g_Vthi[DIM * KT2];                // V^T hi  [o][k-pair]
__device__ unsigned g_Vtlo[DIM * KT2];                // V^T lo  [o][k-pair]

// ============================ helpers ============================

__device__ __forceinline__ uint32_t smem_u32(const void* p) {
    uint32_t a;
    asm("{ .reg .u64 t; cvta.to.shared.u64 t, %1; cvt.u32.u64 %0, t; }"
        : "=r"(a) : "l"(p));
    return a;
}

// bf2(x, y): packed bf16x2 with x in LOW half, y in HIGH half.
__device__ __forceinline__ unsigned bf2(float x, float y) {
    unsigned r;
    asm("cvt.rn.bf16x2.f32 %0, %1, %2;" : "=r"(r) : "f"(y), "f"(x));
    return r;
}
// split_pair: (hi_pair, lo_pair), value = hi + lo (to bf16 rounding of residual)
__device__ __forceinline__ uint2 split_pair(float x, float y) {
    unsigned h = bf2(x, y);
    float rx = x - __uint_as_float(h << 16);           // low bf16 -> f32 (exact)
    float ry = y - __uint_as_float(h & 0xFFFF0000u);   // high bf16 -> f32 (exact)
    unsigned l = bf2(rx, ry);
    return make_uint2(h, l);
}

__device__ __forceinline__ void ldm_x4(uint32_t* r, uint32_t addr) {
    asm volatile("ldmatrix.sync.aligned.m8n8.x4.shared.b16 {%0,%1,%2,%3}, [%4];"
                 : "=r"(r[0]), "=r"(r[1]), "=r"(r[2]), "=r"(r[3]) : "r"(addr));
}
__device__ __forceinline__ void mma_bf16(float* d, const uint32_t* a, const uint32_t* b) {
    asm volatile(
        "mma.sync.aligned.m16n8k16.row.col.f32.bf16.bf16.f32 "
        "{%0,%1,%2,%3}, {%4,%5,%6,%7}, {%8,%9}, {%0,%1,%2,%3};"
        : "+f"(d[0]), "+f"(d[1]), "+f"(d[2]), "+f"(d[3])
        : "r"(a[0]), "r"(a[1]), "r"(a[2]), "r"(a[3]), "r"(b[0]), "r"(b[1]));
}

// ============================ prep kernels ============================

// Vt[o][k] = V[k*128 + o], split into bf16 hi/lo pairs (2 k per thread)
__global__ void vprep_kernel(const float* __restrict__ V) {
    int idx = blockIdx.x * blockDim.x + threadIdx.x;
    if (idx >= DIM * KT2) return;
    int o  = idx >> 8;          // 0..127
    int kp = idx & 255;         // k-pair 0..255
    int k  = kp * 2;
    float v0 = V[(size_t)k * DIM + o];
    float v1 = V[(size_t)(k + 1) * DIM + o];
    uint2 s = split_pair(v0, v1);
    g_Vthi[o * KT2 + kp] = s.x;
    g_Vtlo[o * KT2 + kp] = s.y;
}

__global__ void zero_hist_kernel() {
    int stride = gridDim.x * blockDim.x;
    int tid = blockIdx.x * blockDim.x + threadIdx.x;
    if (tid == 0) g_total = 0;
    for (int i = tid; i < NE; i += stride)
        g_hist[i] = 0;
}

__global__ void hist_kernel(const int* __restrict__ erow) {
    int stride = gridDim.x * blockDim.x;
    for (int i = blockIdx.x * blockDim.x + threadIdx.x; i < NET; i += stride)
        atomicAdd(&g_hist[erow[i]], 1);
}

// segment-offset assignment: warp shfl-scan + one atomic per warp.
// NOT an ordered prefix sum — any disjoint assignment of segments works,
// since g_off/g_cursor/g_hist are the only consumers and stay consistent.
__global__ void offsets_kernel() {
    const int i = blockIdx.x * blockDim.x + threadIdx.x;
    const int lane = threadIdx.x & 31;
    int v = (i < NE) ? g_hist[i] : 0;
    int x = v;
#pragma unroll
    for (int d = 1; d < 32; d <<= 1) {
        int y = __shfl_up_sync(0xFFFFFFFFu, x, d);
        if (lane >= d) x += y;
    }
    int tot = __shfl_sync(0xFFFFFFFFu, x, 31);
    int base = 0;
    if (lane == 0) base = atomicAdd(&g_total, tot);
    base = __shfl_sync(0xFFFFFFFFu, base, 0);
    if (i < NE) {
        int e = base + x - v;
        g_off[i] = e;
        g_cursor[i] = e;
    }
}

__global__ void binsort_kernel(const int* __restrict__ erow,
                               const int* __restrict__ ecol,
                               const float* __restrict__ eval) {
    int stride = gridDim.x * blockDim.x;
    for (int i = blockIdx.x * blockDim.x + threadIdx.x; i < NET; i += stride) {
        int row = erow[i];
        int col = ecol[i];
        float v = eval[i];
        int r = i / NEDGE;
        int pos = atomicAdd(&g_cursor[row], 1);
        ull rec = (ull)(unsigned)(col | (r << 20)) |
                  ((ull)__float_as_uint(v) << 32);
        g_sorted[pos] = rec;
    }
}

// ---- warp per row: accumulate basis-weighted H gathers; write bf16 hi/lo S ----
__global__ __launch_bounds__(256) void gather_kernel(const float* __restrict__ H,
                                                     const float* __restrict__ A) {
    const int lane = threadIdx.x & 31;
    const int w = (blockIdx.x * blockDim.x + threadIdx.x) >> 5;
    float a_reg = __ldg(&A[lane]);   // A is exactly 32 floats [8][4]
    if (w >= NE) return;

    const int off = g_off[w];
    const int cnt = g_hist[w];

    float4 a0 = make_float4(0.f, 0.f, 0.f, 0.f);
    float4 a1 = a0, a2 = a0, a3 = a0;

    int j = 0;
    for (; j + 2 <= cnt; j += 2) {
        ull rec0 = __ldg(&g_sorted[off + j]);
        ull rec1 = __ldg(&g_sorted[off + j + 1]);
        int col0 = (int)(rec0 & 0xFFFFFu);
        int col1 = (int)(rec1 & 0xFFFFFu);
        float4 h0 = __ldg(reinterpret_cast<const float4*>(&H[(size_t)col0 * DIM]) + lane);
        float4 h1 = __ldg(reinterpret_cast<const float4*>(&H[(size_t)col1 * DIM]) + lane);

        {
            int rb = ((int)(rec0 >> 20) & 7) * 4;
            float v = __uint_as_float((unsigned)(rec0 >> 32));
            float c0 = v * __shfl_sync(0xFFFFFFFFu, a_reg, rb + 0);
            float c1 = v * __shfl_sync(0xFFFFFFFFu, a_reg, rb + 1);
            float c2 = v * __shfl_sync(0xFFFFFFFFu, a_reg, rb + 2);
            float c3 = v * __shfl_sync(0xFFFFFFFFu, a_reg, rb + 3);
            a0.x = fmaf(c0, h0.x, a0.x); a0.y = fmaf(c0, h0.y, a0.y);
            a0.z = fmaf(c0, h0.z, a0.z); a0.w = fmaf(c0, h0.w, a0.w);
            a1.x = fmaf(c1, h0.x, a1.x); a1.y = fmaf(c1, h0.y, a1.y);
            a1.z = fmaf(c1, h0.z, a1.z); a1.w = fmaf(c1, h0.w, a1.w);
            a2.x = fmaf(c2, h0.x, a2.x); a2.y = fmaf(c2, h0.y, a2.y);
            a2.z = fmaf(c2, h0.z, a2.z); a2.w = fmaf(c2, h0.w, a2.w);
            a3.x = fmaf(c3, h0.x, a3.x); a3.y = fmaf(c3, h0.y, a3.y);
            a3.z = fmaf(c3, h0.z, a3.z); a3.w = fmaf(c3, h0.w, a3.w);
        }
        {
            int rb = ((int)(rec1 >> 20) & 7) * 4;
            float v = __uint_as_float((unsigned)(rec1 >> 32));
            float c0 = v * __shfl_sync(0xFFFFFFFFu, a_reg, rb + 0);
            float c1 = v * __shfl_sync(0xFFFFFFFFu, a_reg, rb + 1);
            float c2 = v * __shfl_sync(0xFFFFFFFFu, a_reg, rb + 2);
            float c3 = v * __shfl_sync(0xFFFFFFFFu, a_reg, rb + 3);
            a0.x = fmaf(c0, h1.x, a0.x); a0.y = fmaf(c0, h1.y, a0.y);
            a0.z = fmaf(c0, h1.z, a0.z); a0.w = fmaf(c0, h1.w, a0.w);
            a1.x = fmaf(c1, h1.x, a1.x); a1.y = fmaf(c1, h1.y, a1.y);
            a1.z = fmaf(c1, h1.z, a1.z); a1.w = fmaf(c1, h1.w, a1.w);
            a2.x = fmaf(c2, h1.x, a2.x); a2.y = fmaf(c2, h1.y, a2.y);
            a2.z = fmaf(c2, h1.z, a2.z); a2.w = fmaf(c2, h1.w, a2.w);
            a3.x = fmaf(c3, h1.x, a3.x); a3.y = fmaf(c3, h1.y, a3.y);
            a3.z = fmaf(c3, h1.z, a3.z); a3.w = fmaf(c3, h1.w, a3.w);
        }
    }
    if (j < cnt) {
        ull rec = __ldg(&g_sorted[off + j]);
        int col = (int)(rec & 0xFFFFFu);
        int rb  = ((int)(rec >> 20) & 7) * 4;
        float v = __uint_as_float((unsigned)(rec >> 32));
        float c0 = v * __shfl_sync(0xFFFFFFFFu, a_reg, rb + 0);
        float c1 = v * __shfl_sync(0xFFFFFFFFu, a_reg, rb + 1);
        float c2 = v * __shfl_sync(0xFFFFFFFFu, a_reg, rb + 2);
        float c3 = v * __shfl_sync(0xFFFFFFFFu, a_reg, rb + 3);
        float4 h = __ldg(reinterpret_cast<const float4*>(&H[(size_t)col * DIM]) + lane);
        a0.x = fmaf(c0, h.x, a0.x); a0.y = fmaf(c0, h.y, a0.y);
        a0.z = fmaf(c0, h.z, a0.z); a0.w = fmaf(c0, h.w, a0.w);
        a1.x = fmaf(c1, h.x, a1.x); a1.y = fmaf(c1, h.y, a1.y);
        a1.z = fmaf(c1, h.z, a1.z); a1.w = fmaf(c1, h.w, a1.w);
        a2.x = fmaf(c2, h.x, a2.x); a2.y = fmaf(c2, h.y, a2.y);
        a2.z = fmaf(c2, h.z, a2.z); a2.w = fmaf(c2, h.w, a2.w);
        a3.x = fmaf(c3, h.x, a3.x); a3.y = fmaf(c3, h.y, a3.y);
        a3.z = fmaf(c3, h.z, a3.z); a3.w = fmaf(c3, h.w, a3.w);
    }

    // pack to bf16 hi/lo pairs and store (uint2 = 4 bf16)
    uint2* shi = reinterpret_cast<uint2*>(&g_Shi[(size_t)w * KT2]);
    uint2* slo = reinterpret_cast<uint2*>(&g_Slo[(size_t)w * KT2]);
    {
        uint2 p0 = split_pair(a0.x, a0.y);
        uint2 p1 = split_pair(a0.z, a0.w);
        shi[lane] = make_uint2(p0.x, p1.x);
        slo[lane] = make_uint2(p0.y, p1.y);
    }
    {
        uint2 p0 = split_pair(a1.x, a1.y);
        uint2 p1 = split_pair(a1.z, a1.w);
        shi[32 + lane] = make_uint2(p0.x, p1.x);
        slo[32 + lane] = make_uint2(p0.y, p1.y);
    }
    {
        uint2 p0 = split_pair(a2.x, a2.y);
        uint2 p1 = split_pair(a2.z, a2.w);
        shi[64 + lane] = make_uint2(p0.x, p1.x);
        slo[64 + lane] = make_uint2(p0.y, p1.y);
    }
    {
        uint2 p0 = split_pair(a3.x, a3.y);
        uint2 p1 = split_pair(a3.z, a3.w);
        shi[96 + lane] = make_uint2(p0.x, p1.x);
        slo[96 + lane] = make_uint2(p0.y, p1.y);
    }
}

// ============================ mma.sync GEMM ============================
// out[M=100000, N=128] = S[M, K=512] @ Vt^T, split bf16 (3 products),
// fp32 accumulate in registers. m16n8k16 HMMA, CTA tile 128x128, BK=32.
// B stored [n][k] (k contiguous) -> non-transposed ldmatrix for B fragments.
// Global loads for chunk c+1 are prefetched into registers during compute of c.

#define BK       32
#define NCHUNK   (KTOT / BK)    // 16
#define SROW     80             // smem row stride bytes (32 bf16 + 8 pad)

__global__ __launch_bounds__(512, 1) void gemm_mma_kernel(float* __restrict__ out) {
    __shared__ __align__(16) unsigned char smAh[128 * SROW];
    __shared__ __align__(16) unsigned char smAl[128 * SROW];
    __shared__ __align__(16) unsigned char smBh[128 * SROW];
    __shared__ __align__(16) unsigned char smBl[128 * SROW];

    const int t    = threadIdx.x;
    const int lane = t & 31;
    const int wid  = t >> 5;          // 0..15
    const int wm   = wid >> 2;        // 0..3  (M group of 32 rows)
    const int wn   = wid & 3;         // 0..3  (N group of 32 cols)
    const int n0   = blockIdx.x * 128;

    // load mapping: 512 threads, one uint4 per array per thread per chunk
    const int lr = t >> 2;            // row 0..127
    const int lj = t & 3;             // uint4 0..3 within 32-bf16 row chunk
    const int gn = n0 + lr;
    const bool valid = gn < NE;
    const uint4* gAh = reinterpret_cast<const uint4*>(g_Shi) + (size_t)(valid ? gn : 0) * KT4;
    const uint4* gAl = reinterpret_cast<const uint4*>(g_Slo) + (size_t)(valid ? gn : 0) * KT4;
    const uint4* gBh = reinterpret_cast<const uint4*>(g_Vthi) + lr * KT4;
    const uint4* gBl = reinterpret_cast<const uint4*>(g_Vtlo) + lr * KT4;
    unsigned char* stAh = smAh + lr * SROW + lj * 16;
    unsigned char* stAl = smAl + lr * SROW + lj * 16;
    unsigned char* stBh = smBh + lr * SROW + lj * 16;
    unsigned char* stBl = smBl + lr * SROW + lj * 16;
    const uint4 z4 = make_uint4(0u, 0u, 0u, 0u);

    // ldmatrix lane addressing (constant across chunks)
    const uint32_t bAh = smem_u32(smAh), bAl = smem_u32(smAl);
    const uint32_t bBh = smem_u32(smBh), bBl = smem_u32(smBl);
    const int arow = lane & 15, acol = lane >> 4;            // A x4
    const int bgrp = lane >> 3, brow = lane & 7;             // B x4 (non-trans)
    uint32_t aoff[2][2], boff[2][2];
#pragma unroll
    for (int ks2 = 0; ks2 < 2; ks2++) {
#pragma unroll
        for (int mt = 0; mt < 2; mt++)
            aoff[ks2][mt] = (uint32_t)((wm * 32 + mt * 16 + arow) * SROW + ks2 * 32 + acol * 16);
#pragma unroll
        for (int ntp = 0; ntp < 2; ntp++)
            boff[ks2][ntp] = (uint32_t)((wn * 32 + ntp * 16 + (bgrp >> 1) * 8 + brow) * SROW
                                        + ks2 * 32 + (bgrp & 1) * 16);
    }

    float d[2][4][4];
#pragma unroll
    for (int mt = 0; mt < 2; mt++)
#pragma unroll
        for (int nt = 0; nt < 4; nt++)
#pragma unroll
            for (int q = 0; q < 4; q++) d[mt][nt][q] = 0.f;

    // prefetch chunk 0
    uint4 rAh = valid ? __ldg(&gAh[lj]) : z4;
    uint4 rAl = valid ? __ldg(&gAl[lj]) : z4;
    uint4 rBh = __ldg(&gBh[lj]);
    uint4 rBl = __ldg(&gBl[lj]);

    for (int c = 0; c < NCHUNK; c++) {
        __syncthreads();   // previous compute done reading smem
        *reinterpret_cast<uint4*>(stAh) = rAh;
        *reinterpret_cast<uint4*>(stAl) = rAl;
        *reinterpret_cast<uint4*>(stBh) = rBh;
        *reinterpret_cast<uint4*>(stBl) = rBl;
        __syncthreads();

        if (c + 1 < NCHUNK) {           // prefetch next chunk during compute
            rAh = valid ? __ldg(&gAh[(c + 1) * 4 + lj]) : z4;
            rAl = valid ? __ldg(&gAl[(c + 1) * 4 + lj]) : z4;
            rBh = __ldg(&gBh[(c + 1) * 4 + lj]);
            rBl = __ldg(&gBl[(c + 1) * 4 + lj]);
        }

#pragma unroll
        for (int ks2 = 0; ks2 < 2; ks2++) {
            uint32_t a_hi[2][4], a_lo[2][4], b_hi[4][2], b_lo[4][2];
#pragma unroll
            for (int mt = 0; mt < 2; mt++) {
                ldm_x4(a_hi[mt], bAh + aoff[ks2][mt]);
                ldm_x4(a_lo[mt], bAl + aoff[ks2][mt]);
            }
#pragma unroll
            for (int ntp = 0; ntp < 2; ntp++) {
                uint32_t r[4];
                ldm_x4(r, bBh + boff[ks2][ntp]);
                b_hi[ntp * 2][0] = r[0]; b_hi[ntp * 2][1] = r[1];
                b_hi[ntp * 2 + 1][0] = r[2]; b_hi[ntp * 2 + 1][1] = r[3];
                ldm_x4(r, bBl + boff[ks2][ntp]);
                b_lo[ntp * 2][0] = r[0]; b_lo[ntp * 2][1] = r[1];
                b_lo[ntp * 2 + 1][0] = r[2]; b_lo[ntp * 2 + 1][1] = r[3];
            }
#pragma unroll
            for (int mt = 0; mt < 2; mt++)
#pragma unroll
                for (int nt = 0; nt < 4; nt++) {
                    mma_bf16(d[mt][nt], a_hi[mt], b_hi[nt]);
                    mma_bf16(d[mt][nt], a_lo[mt], b_hi[nt]);
                    mma_bf16(d[mt][nt], a_hi[mt], b_lo[nt]);
                }
        }
    }

    // epilogue: fragment (lane) -> rows wm*32+mt*16+{l>>2, l>>2+8}, cols wn*32+nt*8+2*(l&3)
    const int erow = lane >> 2;
    const int ecol = (lane & 3) * 2;
#pragma unroll
    for (int mt = 0; mt < 2; mt++) {
#pragma unroll
        for (int nt = 0; nt < 4; nt++) {
            int r0 = n0 + wm * 32 + mt * 16 + erow;
            int cc = wn * 32 + nt * 8 + ecol;
            if (r0 < NE)
                *reinterpret_cast<float2*>(&out[(size_t)r0 * DIM + cc]) =
                    make_float2(d[mt][nt][0], d[mt][nt][1]);
            if (r0 + 8 < NE)
                *reinterpret_cast<float2*>(&out[(size_t)(r0 + 8) * DIM + cc]) =
                    make_float2(d[mt][nt][2], d[mt][nt][3]);
        }
    }
}

// ============================ launch ============================

extern "C" void kernel_launch(void* const* d_in, const int* in_sizes, int n_in,
                              void* d_out, int out_size) {
    const float* H    = (const float*)d_in[0];
    const float* A    = (const float*)d_in[1];
    const float* V    = (const float*)d_in[2];
    const int*   erow = (const int*)d_in[3];
    const int*   ecol = (const int*)d_in[4];
    const float* eval = (const float*)d_in[5];
    float*       out  = (float*)d_out;

    vprep_kernel<<<(DIM * KT2 + 255) / 256, 256>>>(V);
    zero_hist_kernel<<<196, 512>>>();
    hist_kernel<<<3125, 512>>>(erow);
    offsets_kernel<<<(NE + 255) / 256, 256>>>();
    binsort_kernel<<<3125, 512>>>(erow, ecol, eval);
    gather_kernel<<<(NE * 32 + 255) / 256, 256>>>(H, A);        // launch 5 (ncu)
    gemm_mma_kernel<<<(NE + 127) / 128, 512>>>(out);
}

// round 17
// speedup vs baseline: 3.7291x; 1.1942x over previous
#include <cuda_runtime.h>
#include <cstdint>

#define NE    100000
#define DIM   128
#define NB    4
#define NRL   8
#define NEDGE 200000
#define NET   (NRL * NEDGE)   // 1,600,000 edges total
#define KTOT  (NB * DIM)      // 512
#define KT2   (KTOT / 2)      // 256 uints per row (fp16 pairs)
#define KT4   (KTOT / 8)      // 64 uint4 per row

typedef unsigned long long ull;

// ---- device scratch (allocation-free rule: __device__ globals) ----
__device__ int      g_hist[NE];
__device__ int      g_off[NE];
__device__ int      g_cursor[NE];
__device__ int      g_total;
__device__ ull      g_sorted[NET];                    // packed (col | r<<20, val)
__device__ unsigned g_Sf16[(size_t)NE * KT2];         // 102.4 MB (fp16 pairs)
__device__ unsigned g_Vthi[DIM * KT2];                // V^T hi  [o][k-pair] fp16
__device__ unsigned g_Vtlo[DIM * KT2];                // V^T lo  [o][k-pair] fp16

// ============================ helpers ============================

__device__ __forceinline__ uint32_t smem_u32(const void* p) {
    uint32_t a;
    asm("{ .reg .u64 t; cvta.to.shared.u64 t, %1; cvt.u32.u64 %0, t; }"
        : "=r"(a) : "l"(p));
    return a;
}

// f16p(x, y): packed f16x2 with x in LOW half, y in HIGH half
// (same operand convention as the validated bf16 path).
__device__ __forceinline__ unsigned f16p(float x, float y) {
    unsigned r;
    asm("cvt.rn.f16x2.f32 %0, %1, %2;" : "=r"(r) : "f"(y), "f"(x));
    return r;
}
__device__ __forceinline__ float f16_lo(unsigned u) {
    float f;
    unsigned short h = (unsigned short)(u & 0xFFFFu);
    asm("cvt.f32.f16 %0, %1;" : "=f"(f) : "h"(h));
    return f;
}
__device__ __forceinline__ float f16_hi(unsigned u) {
    float f;
    unsigned short h = (unsigned short)(u >> 16);
    asm("cvt.f32.f16 %0, %1;" : "=f"(f) : "h"(h));
    return f;
}

__device__ __forceinline__ void ldm_x4(uint32_t* r, uint32_t addr) {
    asm volatile("ldmatrix.sync.aligned.m8n8.x4.shared.b16 {%0,%1,%2,%3}, [%4];"
                 : "=r"(r[0]), "=r"(r[1]), "=r"(r[2]), "=r"(r[3]) : "r"(addr));
}
__device__ __forceinline__ void mma_f16(float* d, const uint32_t* a, const uint32_t* b) {
    asm volatile(
        "mma.sync.aligned.m16n8k16.row.col.f32.f16.f16.f32 "
        "{%0,%1,%2,%3}, {%4,%5,%6,%7}, {%8,%9}, {%0,%1,%2,%3};"
        : "+f"(d[0]), "+f"(d[1]), "+f"(d[2]), "+f"(d[3])
        : "r"(a[0]), "r"(a[1]), "r"(a[2]), "r"(a[3]), "r"(b[0]), "r"(b[1]));
}

// ============================ prep kernels ============================

// merged: zero hist + Vt fp16 hi/lo split. Vt[o][k] = V[k*128 + o].
__global__ void prep_kernel(const float* __restrict__ V) {
    int idx = blockIdx.x * blockDim.x + threadIdx.x;
    if (idx == 0) g_total = 0;
    if (idx < NE) g_hist[idx] = 0;
    if (idx < DIM * KT2) {
        int o  = idx >> 8;          // 0..127
        int kp = idx & 255;         // k-pair 0..255
        int k  = kp * 2;
        float v0 = V[(size_t)k * DIM + o];
        float v1 = V[(size_t)(k + 1) * DIM + o];
        unsigned h = f16p(v0, v1);
        float r0 = v0 - f16_lo(h);
        float r1 = v1 - f16_hi(h);
        g_Vthi[o * KT2 + kp] = h;
        g_Vtlo[o * KT2 + kp] = f16p(r0, r1);
    }
}

__global__ void hist_kernel(const int* __restrict__ erow) {
    int stride = gridDim.x * blockDim.x;
    for (int i = blockIdx.x * blockDim.x + threadIdx.x; i < NET; i += stride)
        atomicAdd(&g_hist[erow[i]], 1);
}

// segment-offset assignment: warp shfl-scan + one atomic per warp.
__global__ void offsets_kernel() {
    const int i = blockIdx.x * blockDim.x + threadIdx.x;
    const int lane = threadIdx.x & 31;
    int v = (i < NE) ? g_hist[i] : 0;
    int x = v;
#pragma unroll
    for (int d = 1; d < 32; d <<= 1) {
        int y = __shfl_up_sync(0xFFFFFFFFu, x, d);
        if (lane >= d) x += y;
    }
    int tot = __shfl_sync(0xFFFFFFFFu, x, 31);
    int base = 0;
    if (lane == 0) base = atomicAdd(&g_total, tot);
    base = __shfl_sync(0xFFFFFFFFu, base, 0);
    if (i < NE) {
        int e = base + x - v;
        g_off[i] = e;
        g_cursor[i] = e;
    }
}

__global__ void binsort_kernel(const int* __restrict__ erow,
                               const int* __restrict__ ecol,
                               const float* __restrict__ eval) {
    int stride = gridDim.x * blockDim.x;
    for (int i = blockIdx.x * blockDim.x + threadIdx.x; i < NET; i += stride) {
        int row = erow[i];
        int col = ecol[i];
        float v = eval[i];
        int r = i / NEDGE;
        int pos = atomicAdd(&g_cursor[row], 1);
        ull rec = (ull)(unsigned)(col | (r << 20)) |
                  ((ull)__float_as_uint(v) << 32);
        g_sorted[pos] = rec;
    }
}

// ---- warp per row: accumulate basis-weighted H gathers; write fp16 S ----
__global__ __launch_bounds__(256) void gather_kernel(const float* __restrict__ H,
                                                     const float* __restrict__ A) {
    const int lane = threadIdx.x & 31;
    const int w = (blockIdx.x * blockDim.x + threadIdx.x) >> 5;
    float a_reg = __ldg(&A[lane]);   // A is exactly 32 floats [8][4]
    if (w >= NE) return;

    const int off = g_off[w];
    const int cnt = g_hist[w];

    float4 a0 = make_float4(0.f, 0.f, 0.f, 0.f);
    float4 a1 = a0, a2 = a0, a3 = a0;

    int j = 0;
    for (; j + 2 <= cnt; j += 2) {
        ull rec0 = __ldg(&g_sorted[off + j]);
        ull rec1 = __ldg(&g_sorted[off + j + 1]);
        int col0 = (int)(rec0 & 0xFFFFFu);
        int col1 = (int)(rec1 & 0xFFFFFu);
        float4 h0 = __ldg(reinterpret_cast<const float4*>(&H[(size_t)col0 * DIM]) + lane);
        float4 h1 = __ldg(reinterpret_cast<const float4*>(&H[(size_t)col1 * DIM]) + lane);

        {
            int rb = ((int)(rec0 >> 20) & 7) * 4;
            float v = __uint_as_float((unsigned)(rec0 >> 32));
            float c0 = v * __shfl_sync(0xFFFFFFFFu, a_reg, rb + 0);
            float c1 = v * __shfl_sync(0xFFFFFFFFu, a_reg, rb + 1);
            float c2 = v * __shfl_sync(0xFFFFFFFFu, a_reg, rb + 2);
            float c3 = v * __shfl_sync(0xFFFFFFFFu, a_reg, rb + 3);
            a0.x = fmaf(c0, h0.x, a0.x); a0.y = fmaf(c0, h0.y, a0.y);
            a0.z = fmaf(c0, h0.z, a0.z); a0.w = fmaf(c0, h0.w, a0.w);
            a1.x = fmaf(c1, h0.x, a1.x); a1.y = fmaf(c1, h0.y, a1.y);
            a1.z = fmaf(c1, h0.z, a1.z); a1.w = fmaf(c1, h0.w, a1.w);
            a2.x = fmaf(c2, h0.x, a2.x); a2.y = fmaf(c2, h0.y, a2.y);
            a2.z = fmaf(c2, h0.z, a2.z); a2.w = fmaf(c2, h0.w, a2.w);
            a3.x = fmaf(c3, h0.x, a3.x); a3.y = fmaf(c3, h0.y, a3.y);
            a3.z = fmaf(c3, h0.z, a3.z); a3.w = fmaf(c3, h0.w, a3.w);
        }
        {
            int rb = ((int)(rec1 >> 20) & 7) * 4;
            float v = __uint_as_float((unsigned)(rec1 >> 32));
            float c0 = v * __shfl_sync(0xFFFFFFFFu, a_reg, rb + 0);
            float c1 = v * __shfl_sync(0xFFFFFFFFu, a_reg, rb + 1);
            float c2 = v * __shfl_sync(0xFFFFFFFFu, a_reg, rb + 2);
            float c3 = v * __shfl_sync(0xFFFFFFFFu, a_reg, rb + 3);
            a0.x = fmaf(c0, h1.x, a0.x); a0.y = fmaf(c0, h1.y, a0.y);
            a0.z = fmaf(c0, h1.z, a0.z); a0.w = fmaf(c0, h1.w, a0.w);
            a1.x = fmaf(c1, h1.x, a1.x); a1.y = fmaf(c1, h1.y, a1.y);
            a1.z = fmaf(c1, h1.z, a1.z); a1.w = fmaf(c1, h1.w, a1.w);
            a2.x = fmaf(c2, h1.x, a2.x); a2.y = fmaf(c2, h1.y, a2.y);
            a2.z = fmaf(c2, h1.z, a2.z); a2.w = fmaf(c2, h1.w, a2.w);
            a3.x = fmaf(c3, h1.x, a3.x); a3.y = fmaf(c3, h1.y, a3.y);
            a3.z = fmaf(c3, h1.z, a3.z); a3.w = fmaf(c3, h1.w, a3.w);
        }
    }
    if (j < cnt) {
        ull rec = __ldg(&g_sorted[off + j]);
        int col = (int)(rec & 0xFFFFFu);
        int rb  = ((int)(rec >> 20) & 7) * 4;
        float v = __uint_as_float((unsigned)(rec >> 32));
        float c0 = v * __shfl_sync(0xFFFFFFFFu, a_reg, rb + 0);
        float c1 = v * __shfl_sync(0xFFFFFFFFu, a_reg, rb + 1);
        float c2 = v * __shfl_sync(0xFFFFFFFFu, a_reg, rb + 2);
        float c3 = v * __shfl_sync(0xFFFFFFFFu, a_reg, rb + 3);
        float4 h = __ldg(reinterpret_cast<const float4*>(&H[(size_t)col * DIM]) + lane);
        a0.x = fmaf(c0, h.x, a0.x); a0.y = fmaf(c0, h.y, a0.y);
        a0.z = fmaf(c0, h.z, a0.z); a0.w = fmaf(c0, h.w, a0.w);
        a1.x = fmaf(c1, h.x, a1.x); a1.y = fmaf(c1, h.y, a1.y);
        a1.z = fmaf(c1, h.z, a1.z); a1.w = fmaf(c1, h.w, a1.w);
        a2.x = fmaf(c2, h.x, a2.x); a2.y = fmaf(c2, h.y, a2.y);
        a2.z = fmaf(c2, h.z, a2.z); a2.w = fmaf(c2, h.w, a2.w);
        a3.x = fmaf(c3, h.x, a3.x); a3.y = fmaf(c3, h.y, a3.y);
        a3.z = fmaf(c3, h.z, a3.z); a3.w = fmaf(c3, h.w, a3.w);
    }

    // pack to fp16 pairs and store (uint2 = 4 fp16)
    uint2* s = reinterpret_cast<uint2*>(&g_Sf16[(size_t)w * KT2]);
    s[lane]      = make_uint2(f16p(a0.x, a0.y), f16p(a0.z, a0.w));
    s[32 + lane] = make_uint2(f16p(a1.x, a1.y), f16p(a1.z, a1.w));
    s[64 + lane] = make_uint2(f16p(a2.x, a2.y), f16p(a2.z, a2.w));
    s[96 + lane] = make_uint2(f16p(a3.x, a3.y), f16p(a3.z, a3.w));
}

// ============================ mma.sync GEMM ============================
// out[M=100000, N=128] = S[M, K=512] @ Vt^T, S fp16, V split fp16 hi/lo:
//   S*V_hi + S*V_lo  (fp32 accumulate). m16n8k16 HMMA, CTA 128x128, BK=32.

#define BK       32
#define NCHUNK   (KTOT / BK)    // 16
#define SROW     80             // smem row stride bytes (32 fp16 + 8 pad)

__global__ __launch_bounds__(512, 1) void gemm_mma_kernel(float* __restrict__ out) {
    __shared__ __align__(16) unsigned char smA [128 * SROW];
    __shared__ __align__(16) unsigned char smBh[128 * SROW];
    __shared__ __align__(16) unsigned char smBl[128 * SROW];

    const int t    = threadIdx.x;
    const int lane = t & 31;
    const int wid  = t >> 5;          // 0..15
    const int wm   = wid >> 2;        // 0..3
    const int wn   = wid & 3;         // 0..3
    const int n0   = blockIdx.x * 128;

    const int lr = t >> 2;            // row 0..127
    const int lj = t & 3;             // uint4 0..3 within 64-byte row chunk
    const int gn = n0 + lr;
    const bool valid = gn < NE;
    const uint4* gA  = reinterpret_cast<const uint4*>(g_Sf16) + (size_t)(valid ? gn : 0) * KT4;
    const uint4* gBh = reinterpret_cast<const uint4*>(g_Vthi) + lr * KT4;
    const uint4* gBl = reinterpret_cast<const uint4*>(g_Vtlo) + lr * KT4;
    unsigned char* stA  = smA  + lr * SROW + lj * 16;
    unsigned char* stBh = smBh + lr * SROW + lj * 16;
    unsigned char* stBl = smBl + lr * SROW + lj * 16;
    const uint4 z4 = make_uint4(0u, 0u, 0u, 0u);

    const uint32_t bA = smem_u32(smA), bBh = smem_u32(smBh), bBl = smem_u32(smBl);
    const int arow = lane & 15, acol = lane >> 4;            // A x4
    const int bgrp = lane >> 3, brow = lane & 7;             // B x4 (non-trans)
    uint32_t aoff[2][2], boff[2][2];
#pragma unroll
    for (int ks2 = 0; ks2 < 2; ks2++) {
#pragma unroll
        for (int mt = 0; mt < 2; mt++)
            aoff[ks2][mt] = (uint32_t)((wm * 32 + mt * 16 + arow) * SROW + ks2 * 32 + acol * 16);
#pragma unroll
        for (int ntp = 0; ntp < 2; ntp++)
            boff[ks2][ntp] = (uint32_t)((wn * 32 + ntp * 16 + (bgrp >> 1) * 8 + brow) * SROW
                                        + ks2 * 32 + (bgrp & 1) * 16);
    }

    float d[2][4][4];
#pragma unroll
    for (int mt = 0; mt < 2; mt++)
#pragma unroll
        for (int nt = 0; nt < 4; nt++)
#pragma unroll
            for (int q = 0; q < 4; q++) d[mt][nt][q] = 0.f;

    // prefetch chunk 0
    uint4 rA  = valid ? __ldg(&gA[lj]) : z4;
    uint4 rBh = __ldg(&gBh[lj]);
    uint4 rBl = __ldg(&gBl[lj]);

    for (int c = 0; c < NCHUNK; c++) {
        __syncthreads();
        *reinterpret_cast<uint4*>(stA)  = rA;
        *reinterpret_cast<uint4*>(stBh) = rBh;
        *reinterpret_cast<uint4*>(stBl) = rBl;
        __syncthreads();

        if (c + 1 < NCHUNK) {
            rA  = valid ? __ldg(&gA[(c + 1) * 4 + lj]) : z4;
            rBh = __ldg(&gBh[(c + 1) * 4 + lj]);
            rBl = __ldg(&gBl[(c + 1) * 4 + lj]);
        }

#pragma unroll
        for (int ks2 = 0; ks2 < 2; ks2++) {
            uint32_t a[2][4], b_hi[4][2], b_lo[4][2];
#pragma unroll
            for (int mt = 0; mt < 2; mt++)
                ldm_x4(a[mt], bA + aoff[ks2][mt]);
#pragma unroll
            for (int ntp = 0; ntp < 2; ntp++) {
                uint32_t r[4];
                ldm_x4(r, bBh + boff[ks2][ntp]);
                b_hi[ntp * 2][0] = r[0]; b_hi[ntp * 2][1] = r[1];
                b_hi[ntp * 2 + 1][0] = r[2]; b_hi[ntp * 2 + 1][1] = r[3];
                ldm_x4(r, bBl + boff[ks2][ntp]);
                b_lo[ntp * 2][0] = r[0]; b_lo[ntp * 2][1] = r[1];
                b_lo[ntp * 2 + 1][0] = r[2]; b_lo[ntp * 2 + 1][1] = r[3];
            }
#pragma unroll
            for (int mt = 0; mt < 2; mt++)
#pragma unroll
                for (int nt = 0; nt < 4; nt++) {
                    mma_f16(d[mt][nt], a[mt], b_hi[nt]);
                    mma_f16(d[mt][nt], a[mt], b_lo[nt]);
                }
        }
    }

    // epilogue
    const int erow = lane >> 2;
    const int ecol = (lane & 3) * 2;
#pragma unroll
    for (int mt = 0; mt < 2; mt++) {
#pragma unroll
        for (int nt = 0; nt < 4; nt++) {
            int r0 = n0 + wm * 32 + mt * 16 + erow;
            int cc = wn * 32 + nt * 8 + ecol;
            if (r0 < NE)
                *reinterpret_cast<float2*>(&out[(size_t)r0 * DIM + cc]) =
                    make_float2(d[mt][nt][0], d[mt][nt][1]);
            if (r0 + 8 < NE)
                *reinterpret_cast<float2*>(&out[(size_t)(r0 + 8) * DIM + cc]) =
                    make_float2(d[mt][nt][2], d[mt][nt][3]);
        }
    }
}

// ============================ launch ============================

extern "C" void kernel_launch(void* const* d_in, const int* in_sizes, int n_in,
                              void* d_out, int out_size) {
    const float* H    = (const float*)d_in[0];
    const float* A    = (const float*)d_in[1];
    const float* V    = (const float*)d_in[2];
    const int*   erow = (const int*)d_in[3];
    const int*   ecol = (const int*)d_in[4];
    const float* eval = (const float*)d_in[5];
    float*       out  = (float*)d_out;

    prep_kernel<<<(NE + 255) / 256, 256>>>(V);
    hist_kernel<<<3125, 512>>>(erow);
    offsets_kernel<<<(NE + 255) / 256, 256>>>();
    binsort_kernel<<<3125, 512>>>(erow, ecol, eval);
    gather_kernel<<<(NE * 32 + 255) / 256, 256>>>(H, A);
    gemm_mma_kernel<<<(NE + 127) / 128, 512>>>(out);
}